// round 2
// baseline (speedup 1.0000x reference)
#include <cuda_runtime.h>
#include <cuda_bf16.h>

// Problem constants: B=2, N=2048, E=1024, H=16, D=64
// M = B*N = 4096 flattened rows.

#define CDIV(a, b) (((a) + (b) - 1) / (b))

// Scratch (allocation-free rule: __device__ globals)
__device__ float g_Q[4096 * 1024];   // Q = X @ Wq, laid out (b,n,h,d)
__device__ float g_KV[4096 * 128];   // [K|V] = X @ [Wk|Wv], per row: 64 K + 64 V
__device__ float g_Z[4096 * 1024];   // attention output (b,n,h,d)
__device__ float g_Wkv[1024 * 128];  // concatenated [Wk|Wv]

// ---------------------------------------------------------------------------
// Concatenate Wk (1024x64) and Wv (1024x64) into Wkv (1024x128)
// ---------------------------------------------------------------------------
__global__ void concat_kv_kernel(const float* __restrict__ Wk,
                                 const float* __restrict__ Wv,
                                 float* __restrict__ Wkv) {
    int i = blockIdx.x * 256 + threadIdx.x;
    if (i < 1024 * 64) {
        int r = i >> 6;
        int c = i & 63;
        Wkv[r * 128 + c]      = Wk[i];
        Wkv[r * 128 + 64 + c] = Wv[i];
    }
}

// ---------------------------------------------------------------------------
// SGEMM: C[M,N] = A[M,K] @ B[K,N] (+ bias[N]), row-major, fp32.
// BM=BN=128, BK=8, 256 threads, 8x8 microtile per thread.
// Requires M%128==0, N%128==0, K%8==0 (true for all calls here).
// ---------------------------------------------------------------------------
__global__ __launch_bounds__(256)
void sgemm128(const float* __restrict__ A, const float* __restrict__ B,
              float* __restrict__ C, const float* __restrict__ bias,
              int M, int N, int K) {
    __shared__ float As[8 * 128];  // transposed: As[k][m]
    __shared__ float Bs[8 * 128];  // Bs[k][n]

    const int tid  = threadIdx.x;
    const int cRow = blockIdx.y * 128;
    const int cCol = blockIdx.x * 128;

    const int tCol = (tid & 15) * 8;   // 16 thread-cols * 8
    const int tRow = (tid >> 4) * 8;   // 16 thread-rows * 8

    // A tile load: 128 rows x 8 cols = 256 float4 (one per thread)
    const int aRow = tid >> 1;          // 0..127
    const int aCol = (tid & 1) * 4;     // 0 or 4
    // B tile load: 8 rows x 128 cols = 256 float4
    const int bRow = tid >> 5;          // 0..7
    const int bCol = (tid & 31) * 4;    // 0..124

    const float* Ap = A + (size_t)(cRow + aRow) * K + aCol;
    const float* Bp = B + (size_t)bRow * N + cCol + bCol;

    float acc[8][8];
#pragma unroll
    for (int i = 0; i < 8; i++)
#pragma unroll
        for (int j = 0; j < 8; j++) acc[i][j] = 0.0f;

    for (int k0 = 0; k0 < K; k0 += 8) {
        float4 a4 = *(const float4*)(Ap + k0);
        As[(aCol + 0) * 128 + aRow] = a4.x;
        As[(aCol + 1) * 128 + aRow] = a4.y;
        As[(aCol + 2) * 128 + aRow] = a4.z;
        As[(aCol + 3) * 128 + aRow] = a4.w;
        float4 b4 = *(const float4*)(Bp + (size_t)k0 * N);
        *(float4*)&Bs[bRow * 128 + bCol] = b4;
        __syncthreads();

#pragma unroll
        for (int k = 0; k < 8; k++) {
            float rm[8], rn[8];
            *(float4*)&rm[0] = *(const float4*)&As[k * 128 + tRow];
            *(float4*)&rm[4] = *(const float4*)&As[k * 128 + tRow + 4];
            *(float4*)&rn[0] = *(const float4*)&Bs[k * 128 + tCol];
            *(float4*)&rn[4] = *(const float4*)&Bs[k * 128 + tCol + 4];
#pragma unroll
            for (int i = 0; i < 8; i++)
#pragma unroll
                for (int j = 0; j < 8; j++) acc[i][j] += rm[i] * rn[j];
        }
        __syncthreads();
    }

#pragma unroll
    for (int i = 0; i < 8; i++) {
        int row = cRow + tRow + i;
#pragma unroll
        for (int j = 0; j < 8; j += 4) {
            int col = cCol + tCol + j;
            float4 v;
            v.x = acc[i][j + 0];
            v.y = acc[i][j + 1];
            v.z = acc[i][j + 2];
            v.w = acc[i][j + 3];
            if (bias != nullptr) {
                float4 bb = *(const float4*)&bias[col];
                v.x += bb.x; v.y += bb.y; v.z += bb.z; v.w += bb.w;
            }
            *(float4*)&C[(size_t)row * N + col] = v;
        }
    }
}

// ---------------------------------------------------------------------------
// Causal flash-attention (MQA): one block per (qtile, h, b), 64 threads,
// one thread per query row. K/V shared across heads (MQA).
// Q: (b,n,h,d) at g_Q[(b*2048+n)*1024 + h*64 + d]
// KV: g_KV[(b*2048+m)*128 + d] = K, +64+d = V
// Z: same layout as Q.
// ---------------------------------------------------------------------------
__global__ __launch_bounds__(64)
void attn_kernel(const float* __restrict__ Q, const float* __restrict__ KV,
                 float* __restrict__ Z) {
    __shared__ float K_s[64 * 64];
    __shared__ float V_s[64 * 64];
    __shared__ float S_s[64 * 64];

    const int t     = threadIdx.x;      // query row within tile
    const int qtile = blockIdx.x;       // 0..31
    const int h     = blockIdx.y;       // 0..15
    const int b     = blockIdx.z;       // 0..1
    const int n     = qtile * 64 + t;   // global query index within batch

    const float* qptr = Q + ((size_t)(b * 2048 + n)) * 1024 + h * 64;

    float q[64], o[64];
#pragma unroll
    for (int d4 = 0; d4 < 16; d4++) {
        float4 v = ((const float4*)qptr)[d4];
        // fold in the 1/sqrt(D) = 1/8 scale here
        q[4 * d4 + 0] = v.x * 0.125f;
        q[4 * d4 + 1] = v.y * 0.125f;
        q[4 * d4 + 2] = v.z * 0.125f;
        q[4 * d4 + 3] = v.w * 0.125f;
    }
#pragma unroll
    for (int d = 0; d < 64; d++) o[d] = 0.0f;

    float m = -1e30f;
    float l = 0.0f;

    const float* kvbase = KV + (size_t)b * 2048 * 128;

    for (int jt = 0; jt <= qtile; jt++) {
        // cooperative tile load: thread t loads KV row (jt*64 + t), swizzled
        const float* krow = kvbase + (size_t)(jt * 64 + t) * 128;
#pragma unroll
        for (int d4 = 0; d4 < 16; d4++) {
            int d  = d4 * 4;
            int sw = (d + 4 * t) & 63;  // bank swizzle, float4-aligned
            *(float4*)&K_s[t * 64 + sw] = *(const float4*)&krow[d];
            *(float4*)&V_s[t * 64 + sw] = *(const float4*)&krow[64 + d];
        }
        __syncthreads();

        const bool diag = (jt == qtile);

        // Pass 1: scores for this row, track running max, stage in SMEM
        float mt = -1e30f;
        for (int j = 0; j < 64; j++) {
            const float* krow_s = &K_s[j * 64];
            const int jb = 4 * j;
            float acc = 0.0f;
#pragma unroll
            for (int d4 = 0; d4 < 16; d4++) {
                int d = d4 * 4;
                float4 kv = *(const float4*)&krow_s[(d + jb) & 63];
                acc += q[d + 0] * kv.x;
                acc += q[d + 1] * kv.y;
                acc += q[d + 2] * kv.z;
                acc += q[d + 3] * kv.w;
            }
            if (diag && j > t) acc = -1e30f;  // causal mask
            mt = fmaxf(mt, acc);
            S_s[t * 64 + ((j + t) & 63)] = acc;
        }

        const float m_new = fmaxf(m, mt);
        const float alpha = __expf(m - m_new);
        l *= alpha;
#pragma unroll
        for (int d = 0; d < 64; d++) o[d] *= alpha;

        // Pass 2: exponentiate + accumulate P @ V
        for (int j = 0; j < 64; j++) {
            float p = __expf(S_s[t * 64 + ((j + t) & 63)] - m_new);
            l += p;
            const float* vrow_s = &V_s[j * 64];
            const int jb = 4 * j;
#pragma unroll
            for (int d4 = 0; d4 < 16; d4++) {
                int d = d4 * 4;
                float4 vv = *(const float4*)&vrow_s[(d + jb) & 63];
                o[d + 0] += p * vv.x;
                o[d + 1] += p * vv.y;
                o[d + 2] += p * vv.z;
                o[d + 3] += p * vv.w;
            }
        }
        m = m_new;
        __syncthreads();
    }

    const float inv_l = 1.0f / l;
    float* zptr = Z + ((size_t)(b * 2048 + n)) * 1024 + h * 64;
#pragma unroll
    for (int d4 = 0; d4 < 16; d4++) {
        int d = d4 * 4;
        float4 v;
        v.x = o[d + 0] * inv_l;
        v.y = o[d + 1] * inv_l;
        v.z = o[d + 2] * inv_l;
        v.w = o[d + 3] * inv_l;
        ((float4*)zptr)[d4] = v;
    }
}

// ---------------------------------------------------------------------------
// Launch
// ---------------------------------------------------------------------------
extern "C" void kernel_launch(void* const* d_in, const int* in_sizes, int n_in,
                              void* d_out, int out_size) {
    const float* x  = (const float*)d_in[0];  // (2,2048,1024)
    const float* Wq = (const float*)d_in[1];  // (1024,1024)
    const float* Wk = (const float*)d_in[2];  // (1024,64)
    const float* Wv = (const float*)d_in[3];  // (1024,64)
    const float* Wo = (const float*)d_in[4];  // (1024,1024)
    const float* bo = (const float*)d_in[5];  // (1024,)

    float *Qp, *KVp, *Zp, *Wkvp;
    cudaGetSymbolAddress((void**)&Qp,   g_Q);
    cudaGetSymbolAddress((void**)&KVp,  g_KV);
    cudaGetSymbolAddress((void**)&Zp,   g_Z);
    cudaGetSymbolAddress((void**)&Wkvp, g_Wkv);

    // 1) concat [Wk|Wv]
    concat_kv_kernel<<<CDIV(1024 * 64, 256), 256>>>(Wk, Wv, Wkvp);

    // 2) Q = X @ Wq   (4096x1024 @ 1024x1024)
    sgemm128<<<dim3(1024 / 128, 4096 / 128), 256>>>(x, Wq, Qp, nullptr,
                                                    4096, 1024, 1024);

    // 3) KV = X @ [Wk|Wv]  (4096x1024 @ 1024x128)
    sgemm128<<<dim3(128 / 128, 4096 / 128), 256>>>(x, Wkvp, KVp, nullptr,
                                                   4096, 128, 1024);

    // 4) causal flash-attention MQA
    attn_kernel<<<dim3(32, 16, 2), 64>>>(Qp, KVp, Zp);

    // 5) out = Z @ Wo + bo  -> d_out directly
    sgemm128<<<dim3(1024 / 128, 4096 / 128), 256>>>(Zp, Wo, (float*)d_out, bo,
                                                    4096, 1024, 1024);
}

// round 8
// speedup vs baseline: 1.1207x; 1.1207x over previous
#include <cuda_runtime.h>
#include <cuda_bf16.h>
#include <cstdint>

// Problem constants: B=2, N=2048, E=1024, H=16, D=64
// M = B*N = 4096 flattened rows. QKV fused width = 1024 + 64 + 64 = 1152.

#define CDIV(a, b) (((a) + (b) - 1) / (b))

// ---------------------------------------------------------------------------
// Scratch (__device__ globals; allocation-free rule)
// ---------------------------------------------------------------------------
__device__ float           g_QKV[4096 * 1152];   // [Q | K | V] per row
__device__ float           g_Z[4096 * 1024];     // attention output
__device__ __nv_bfloat16   g_Xhi[4096 * 1024];
__device__ __nv_bfloat16   g_Xlo[4096 * 1024];
__device__ __nv_bfloat16   g_Wthi[1152 * 1024];  // [Wq|Wk|Wv]^T  (N-major, K contiguous)
__device__ __nv_bfloat16   g_Wtlo[1152 * 1024];
__device__ __nv_bfloat16   g_Wothi[1024 * 1024]; // Wo^T
__device__ __nv_bfloat16   g_Wotlo[1024 * 1024];
__device__ __nv_bfloat16   g_Zhi[4096 * 1024];
__device__ __nv_bfloat16   g_Zlo[4096 * 1024];

// ---------------------------------------------------------------------------
// Helpers
// ---------------------------------------------------------------------------
__device__ __forceinline__ uint32_t smem_to_u32(const void* p) {
    uint32_t a;
    asm("{ .reg .u64 t; cvta.to.shared.u64 t, %1; cvt.u32.u64 %0, t; }"
        : "=r"(a) : "l"(p));
    return a;
}

__device__ __forceinline__ void ldmatrix_x4(uint32_t* r, uint32_t addr) {
    asm volatile(
        "ldmatrix.sync.aligned.m8n8.x4.shared.b16 {%0, %1, %2, %3}, [%4];"
        : "=r"(r[0]), "=r"(r[1]), "=r"(r[2]), "=r"(r[3]) : "r"(addr));
}

__device__ __forceinline__ void mma_bf16(float* d, const uint32_t* a,
                                         uint32_t b0, uint32_t b1) {
    asm volatile(
        "mma.sync.aligned.m16n8k16.row.col.f32.bf16.bf16.f32 "
        "{%0, %1, %2, %3}, {%4, %5, %6, %7}, {%8, %9}, {%0, %1, %2, %3};"
        : "+f"(d[0]), "+f"(d[1]), "+f"(d[2]), "+f"(d[3])
        : "r"(a[0]), "r"(a[1]), "r"(a[2]), "r"(a[3]), "r"(b0), "r"(b1));
}

// ---------------------------------------------------------------------------
// Precision-split conversion: x -> hi = bf16(x), lo = bf16(x - hi)
// ---------------------------------------------------------------------------
__global__ void split_f32_bf16(const float* __restrict__ x,
                               __nv_bfloat16* __restrict__ hi,
                               __nv_bfloat16* __restrict__ lo, int n4) {
    int i = blockIdx.x * 256 + threadIdx.x;
    if (i >= n4) return;
    float4 v = ((const float4*)x)[i];
    __nv_bfloat16 h0 = __float2bfloat16(v.x), h1 = __float2bfloat16(v.y);
    __nv_bfloat16 h2 = __float2bfloat16(v.z), h3 = __float2bfloat16(v.w);
    __nv_bfloat16 l0 = __float2bfloat16(v.x - __bfloat162float(h0));
    __nv_bfloat16 l1 = __float2bfloat16(v.y - __bfloat162float(h1));
    __nv_bfloat16 l2 = __float2bfloat16(v.z - __bfloat162float(h2));
    __nv_bfloat16 l3 = __float2bfloat16(v.w - __bfloat162float(h3));
    ((__nv_bfloat162*)hi)[2 * i + 0] = __halves2bfloat162(h0, h1);
    ((__nv_bfloat162*)hi)[2 * i + 1] = __halves2bfloat162(h2, h3);
    ((__nv_bfloat162*)lo)[2 * i + 0] = __halves2bfloat162(l0, l1);
    ((__nv_bfloat162*)lo)[2 * i + 1] = __halves2bfloat162(l2, l3);
}

// Build W_all^T (1152 x 1024) split into hi/lo.  Row n of output:
//   n < 1024  -> Wq[:, n];  1024 <= n < 1088 -> Wk[:, n-1024];  else Wv[:, n-1088]
__global__ void build_wall_t(const float* __restrict__ Wq,
                             const float* __restrict__ Wk,
                             const float* __restrict__ Wv,
                             __nv_bfloat16* __restrict__ hi,
                             __nv_bfloat16* __restrict__ lo) {
    int i = blockIdx.x * 256 + threadIdx.x;
    if (i >= 1152 * 1024) return;
    int n = i >> 10;
    int k = i & 1023;
    float v;
    if (n < 1024)      v = Wq[k * 1024 + n];
    else if (n < 1088) v = Wk[k * 64 + (n - 1024)];
    else               v = Wv[k * 64 + (n - 1088)];
    __nv_bfloat16 h = __float2bfloat16(v);
    hi[i] = h;
    lo[i] = __float2bfloat16(v - __bfloat162float(h));
}

// Wo^T (1024 x 1024) split into hi/lo
__global__ void build_wo_t(const float* __restrict__ Wo,
                           __nv_bfloat16* __restrict__ hi,
                           __nv_bfloat16* __restrict__ lo) {
    int i = blockIdx.x * 256 + threadIdx.x;
    if (i >= 1024 * 1024) return;
    int n = i >> 10;
    int k = i & 1023;
    float v = Wo[k * 1024 + n];
    __nv_bfloat16 h = __float2bfloat16(v);
    hi[i] = h;
    lo[i] = __float2bfloat16(v - __bfloat162float(h));
}

// ---------------------------------------------------------------------------
// HMMA GEMM (mma.sync m16n8k16 bf16, split precision x3):
//   C[128*by : +128, 128*bx : +128] = (Ahi+Alo) . (Bhi+Blo)^T (+ bias), fp32.
// A row-major [M x K] bf16; B given K-major per row: Bt[n][k].
// 256 threads, 8 warps as 4(row) x 2(col); warp tile 32x64.
// SMEM tiles padded to stride 40 bf16 (80 B) -> conflict-free ldmatrix.
// ---------------------------------------------------------------------------
#define LDT 40

__global__ __launch_bounds__(256, 2)
void hmma_gemm(const __nv_bfloat16* __restrict__ Ahi, const __nv_bfloat16* __restrict__ Alo,
               const __nv_bfloat16* __restrict__ Bhi, const __nv_bfloat16* __restrict__ Blo,
               float* __restrict__ C, const float* __restrict__ bias,
               int K, int ldc) {
    __shared__ __nv_bfloat16 sAhi[128 * LDT];
    __shared__ __nv_bfloat16 sAlo[128 * LDT];
    __shared__ __nv_bfloat16 sBhi[128 * LDT];
    __shared__ __nv_bfloat16 sBlo[128 * LDT];

    const int tid  = threadIdx.x;
    const int lane = tid & 31;
    const int wid  = tid >> 5;
    const int warp_row = wid & 3;   // 4 row groups of 32
    const int warp_col = wid >> 2;  // 2 col groups of 64

    const int cRow = blockIdx.y * 128;
    const int cCol = blockIdx.x * 128;

    // Loader mapping: 256 threads; row = tid>>1 (0..127), seg = tid&1 (16 bf16 each)
    const int lrow = tid >> 1;
    const int seg  = (tid & 1) * 16;
    const __nv_bfloat16* gAhi = Ahi + (size_t)(cRow + lrow) * K + seg;
    const __nv_bfloat16* gAlo = Alo + (size_t)(cRow + lrow) * K + seg;
    const __nv_bfloat16* gBhi = Bhi + (size_t)(cCol + lrow) * K + seg;
    const __nv_bfloat16* gBlo = Blo + (size_t)(cCol + lrow) * K + seg;
    __nv_bfloat16* stA_hi = &sAhi[lrow * LDT + seg];
    __nv_bfloat16* stA_lo = &sAlo[lrow * LDT + seg];
    __nv_bfloat16* stB_hi = &sBhi[lrow * LDT + seg];
    __nv_bfloat16* stB_lo = &sBlo[lrow * LDT + seg];

    // ldmatrix lane base offsets (bytes)
    // A (m16x k16 tile): lanes 0-15 -> rows m0-15 @ k0-7; lanes 16-31 -> rows @ k8-15
    const uint32_t aoff =
        ((uint32_t)(warp_row * 32 + (lane & 15)) * LDT + ((lane >> 4) << 3)) * 2;
    // B (two n8 tiles x k16): lanes 0-7: n0-7 k0-7; 8-15: n0-7 k8-15;
    //                         16-23: n8-15 k0-7; 24-31: n8-15 k8-15
    const uint32_t boff =
        ((uint32_t)(warp_col * 64 + (lane & 7) + ((lane >> 4) << 3)) * LDT +
         (((lane >> 3) & 1) << 3)) * 2;

    const uint32_t sAhi_b = smem_to_u32(sAhi), sAlo_b = smem_to_u32(sAlo);
    const uint32_t sBhi_b = smem_to_u32(sBhi), sBlo_b = smem_to_u32(sBlo);

    float acc[2][8][4];
#pragma unroll
    for (int mi = 0; mi < 2; mi++)
#pragma unroll
        for (int ni = 0; ni < 8; ni++)
#pragma unroll
            for (int j = 0; j < 4; j++) acc[mi][ni][j] = 0.0f;

    for (int k0 = 0; k0 < K; k0 += 32) {
        // ---- load tiles (2 x uint4 per tile per thread) ----
        *(uint4*)(stA_hi)     = *(const uint4*)(gAhi + k0);
        *(uint4*)(stA_hi + 8) = *(const uint4*)(gAhi + k0 + 8);
        *(uint4*)(stA_lo)     = *(const uint4*)(gAlo + k0);
        *(uint4*)(stA_lo + 8) = *(const uint4*)(gAlo + k0 + 8);
        *(uint4*)(stB_hi)     = *(const uint4*)(gBhi + k0);
        *(uint4*)(stB_hi + 8) = *(const uint4*)(gBhi + k0 + 8);
        *(uint4*)(stB_lo)     = *(const uint4*)(gBlo + k0);
        *(uint4*)(stB_lo + 8) = *(const uint4*)(gBlo + k0 + 8);
        __syncthreads();

#pragma unroll
        for (int ks = 0; ks < 2; ks++) {
            uint32_t ahi[2][4], alo[2][4];
#pragma unroll
            for (int mi = 0; mi < 2; mi++) {
                const uint32_t o = aoff + (uint32_t)(mi * 16 * LDT + ks * 16) * 2;
                ldmatrix_x4(ahi[mi], sAhi_b + o);
                ldmatrix_x4(alo[mi], sAlo_b + o);
            }
#pragma unroll
            for (int g = 0; g < 4; g++) {
                uint32_t bhi[4], blo[4];
                const uint32_t o = boff + (uint32_t)(g * 16 * LDT + ks * 16) * 2;
                ldmatrix_x4(bhi, sBhi_b + o);
                ldmatrix_x4(blo, sBlo_b + o);
#pragma unroll
                for (int mi = 0; mi < 2; mi++) {
                    mma_bf16(acc[mi][2 * g + 0], ahi[mi], bhi[0], bhi[1]);
                    mma_bf16(acc[mi][2 * g + 0], ahi[mi], blo[0], blo[1]);
                    mma_bf16(acc[mi][2 * g + 0], alo[mi], bhi[0], bhi[1]);
                    mma_bf16(acc[mi][2 * g + 1], ahi[mi], bhi[2], bhi[3]);
                    mma_bf16(acc[mi][2 * g + 1], ahi[mi], blo[2], blo[3]);
                    mma_bf16(acc[mi][2 * g + 1], alo[mi], bhi[2], bhi[3]);
                }
            }
        }
        __syncthreads();
    }

    // ---- epilogue ----
    // acc[mi][ni]: rows m = warp_row*32 + mi*16 + lane/4 (+8 for regs 2,3),
    //              cols n = warp_col*64 + ni*8 + (lane%4)*2 (+1)
#pragma unroll
    for (int mi = 0; mi < 2; mi++) {
        const int row = cRow + warp_row * 32 + mi * 16 + (lane >> 2);
#pragma unroll
        for (int ni = 0; ni < 8; ni++) {
            const int col = cCol + warp_col * 64 + ni * 8 + (lane & 3) * 2;
            float2 v0 = make_float2(acc[mi][ni][0], acc[mi][ni][1]);
            float2 v1 = make_float2(acc[mi][ni][2], acc[mi][ni][3]);
            if (bias != nullptr) {
                float2 bb = *(const float2*)&bias[col];
                v0.x += bb.x; v0.y += bb.y;
                v1.x += bb.x; v1.y += bb.y;
            }
            *(float2*)&C[(size_t)row * ldc + col]       = v0;
            *(float2*)&C[(size_t)(row + 8) * ldc + col] = v1;
        }
    }
}

// ---------------------------------------------------------------------------
// Causal flash-attention (MQA): one block per (qtile, h, b), 128 threads,
// a LANE PAIR per query row (thread handles 32 of 64 d-channels).
// QKV row stride 1152: Q at col h*64, K at col 1024, V at col 1088.
// ---------------------------------------------------------------------------
__global__ __launch_bounds__(128)
void attn_kernel(const float* __restrict__ QKV, float* __restrict__ Z) {
    __shared__ float K_s[64 * 64];
    __shared__ float V_s[64 * 64];
    __shared__ float S_s[64 * 64];

    const int tid   = threadIdx.x;
    const int r     = tid >> 1;     // query row within tile (0..63)
    const int half  = tid & 1;      // which 32 d-channels
    const int qtile = blockIdx.x;
    const int h     = blockIdx.y;
    const int b     = blockIdx.z;
    const int n     = qtile * 64 + r;
    const int dbase = half * 32;

    const float* qptr = QKV + ((size_t)(b * 2048 + n)) * 1152 + h * 64 + dbase;

    float q[32], o[32];
#pragma unroll
    for (int d4 = 0; d4 < 8; d4++) {
        float4 v = ((const float4*)qptr)[d4];
        q[4 * d4 + 0] = v.x * 0.125f;   // fold 1/sqrt(64)
        q[4 * d4 + 1] = v.y * 0.125f;
        q[4 * d4 + 2] = v.z * 0.125f;
        q[4 * d4 + 3] = v.w * 0.125f;
    }
#pragma unroll
    for (int d = 0; d < 32; d++) o[d] = 0.0f;

    float m = -1e30f;
    float l = 0.0f;

    const float* kvbase = QKV + (size_t)b * 2048 * 1152 + 1024;

    for (int jt = 0; jt <= qtile; jt++) {
        // cooperative load: lane pair loads KV row (jt*64 + r), each its half
        const float* kbase = kvbase + (size_t)(jt * 64 + r) * 1152;
#pragma unroll
        for (int d4 = 0; d4 < 8; d4++) {
            int d  = dbase + d4 * 4;
            int sw = (d + 4 * r) & 63;
            *(float4*)&K_s[r * 64 + sw] = *(const float4*)&kbase[d];
            *(float4*)&V_s[r * 64 + sw] = *(const float4*)&kbase[64 + d];
        }
        __syncthreads();

        const bool diag = (jt == qtile);

        // Pass 1: half-dot + pair shuffle-combine; stage scores in SMEM
        float mt = -1e30f;
        for (int j = 0; j < 64; j++) {
            const float* krow_s = &K_s[j * 64];
            const int jb = 4 * j;
            float pa = 0.0f;
#pragma unroll
            for (int d4 = 0; d4 < 8; d4++) {
                int d = dbase + d4 * 4;
                float4 kv = *(const float4*)&krow_s[(d + jb) & 63];
                pa += q[4 * d4 + 0] * kv.x;
                pa += q[4 * d4 + 1] * kv.y;
                pa += q[4 * d4 + 2] * kv.z;
                pa += q[4 * d4 + 3] * kv.w;
            }
            float s = pa + __shfl_xor_sync(0xffffffffu, pa, 1);
            if (diag && j > r) s = -1e30f;
            mt = fmaxf(mt, s);
            if (!half) S_s[r * 64 + ((j + r) & 63)] = s;
        }
        __syncwarp();

        const float m_new = fmaxf(m, mt);
        const float alpha = __expf(m - m_new);
        l *= alpha;
#pragma unroll
        for (int d = 0; d < 32; d++) o[d] *= alpha;

        // Pass 2: exponentiate + accumulate P @ V (this thread's 32 channels)
        for (int j = 0; j < 64; j++) {
            float p = __expf(S_s[r * 64 + ((j + r) & 63)] - m_new);
            l += p;
            const float* vrow_s = &V_s[j * 64];
            const int jb = 4 * j;
#pragma unroll
            for (int d4 = 0; d4 < 8; d4++) {
                int d = dbase + d4 * 4;
                float4 vv = *(const float4*)&vrow_s[(d + jb) & 63];
                o[4 * d4 + 0] += p * vv.x;
                o[4 * d4 + 1] += p * vv.y;
                o[4 * d4 + 2] += p * vv.z;
                o[4 * d4 + 3] += p * vv.w;
            }
        }
        m = m_new;
        __syncthreads();
    }

    const float inv_l = 1.0f / l;
    float* zptr = Z + ((size_t)(b * 2048 + n)) * 1024 + h * 64 + dbase;
#pragma unroll
    for (int d4 = 0; d4 < 8; d4++) {
        float4 v;
        v.x = o[4 * d4 + 0] * inv_l;
        v.y = o[4 * d4 + 1] * inv_l;
        v.z = o[4 * d4 + 2] * inv_l;
        v.w = o[4 * d4 + 3] * inv_l;
        ((float4*)zptr)[d4] = v;
    }
}

// ---------------------------------------------------------------------------
// Launch
// ---------------------------------------------------------------------------
extern "C" void kernel_launch(void* const* d_in, const int* in_sizes, int n_in,
                              void* d_out, int out_size) {
    const float* x  = (const float*)d_in[0];  // (2,2048,1024)
    const float* Wq = (const float*)d_in[1];  // (1024,1024)
    const float* Wk = (const float*)d_in[2];  // (1024,64)
    const float* Wv = (const float*)d_in[3];  // (1024,64)
    const float* Wo = (const float*)d_in[4];  // (1024,1024)
    const float* bo = (const float*)d_in[5];  // (1024,)

    float *QKVp, *Zp;
    __nv_bfloat16 *Xhi, *Xlo, *Wthi, *Wtlo, *Wothi, *Wotlo, *Zhi, *Zlo;
    cudaGetSymbolAddress((void**)&QKVp,  g_QKV);
    cudaGetSymbolAddress((void**)&Zp,    g_Z);
    cudaGetSymbolAddress((void**)&Xhi,   g_Xhi);
    cudaGetSymbolAddress((void**)&Xlo,   g_Xlo);
    cudaGetSymbolAddress((void**)&Wthi,  g_Wthi);
    cudaGetSymbolAddress((void**)&Wtlo,  g_Wtlo);
    cudaGetSymbolAddress((void**)&Wothi, g_Wothi);
    cudaGetSymbolAddress((void**)&Wotlo, g_Wotlo);
    cudaGetSymbolAddress((void**)&Zhi,   g_Zhi);
    cudaGetSymbolAddress((void**)&Zlo,   g_Zlo);

    // 1) precision-split inputs / weights
    split_f32_bf16<<<CDIV(4096 * 1024 / 4, 256), 256>>>(x, Xhi, Xlo, 4096 * 1024 / 4);
    build_wall_t<<<CDIV(1152 * 1024, 256), 256>>>(Wq, Wk, Wv, Wthi, Wtlo);
    build_wo_t<<<CDIV(1024 * 1024, 256), 256>>>(Wo, Wothi, Wotlo);

    // 2) QKV = X @ [Wq|Wk|Wv]   (4096 x 1152, K = 1024) on HMMA
    hmma_gemm<<<dim3(1152 / 128, 4096 / 128), 256>>>(
        Xhi, Xlo, Wthi, Wtlo, QKVp, nullptr, 1024, 1152);

    // 3) causal flash-attention MQA
    attn_kernel<<<dim3(32, 16, 2), 128>>>(QKVp, Zp);

    // 4) split Z, then out = Z @ Wo + bo -> d_out on HMMA
    split_f32_bf16<<<CDIV(4096 * 1024 / 4, 256), 256>>>(Zp, Zhi, Zlo, 4096 * 1024 / 4);
    hmma_gemm<<<dim3(1024 / 128, 4096 / 128), 256>>>(
        Zhi, Zlo, Wothi, Wotlo, (float*)d_out, bo, 1024, 1024);
}

// round 12
// speedup vs baseline: 3.7775x; 3.3706x over previous
#include <cuda_runtime.h>
#include <cuda_bf16.h>
#include <cstdint>

// Problem constants: B=2, N=2048, E=1024, H=16, D=64
// M = B*N = 4096 flattened rows. QKV fused width = 1024 + 64 + 64 = 1152.

#define CDIV(a, b) (((a) + (b) - 1) / (b))

// ---------------------------------------------------------------------------
// Scratch (__device__ globals; allocation-free rule)
// ---------------------------------------------------------------------------
__device__ float           g_QKV[4096 * 1152];   // [Q | K | V] per row
__device__ float           g_Z[4096 * 1024];     // attention output
__device__ __nv_bfloat16   g_Xhi[4096 * 1024];
__device__ __nv_bfloat16   g_Xlo[4096 * 1024];
__device__ __nv_bfloat16   g_Wthi[1152 * 1024];  // [Wq|Wk|Wv]^T  (N-major, K contiguous)
__device__ __nv_bfloat16   g_Wtlo[1152 * 1024];
__device__ __nv_bfloat16   g_Wothi[1024 * 1024]; // Wo^T
__device__ __nv_bfloat16   g_Wotlo[1024 * 1024];
__device__ __nv_bfloat16   g_Zhi[4096 * 1024];
__device__ __nv_bfloat16   g_Zlo[4096 * 1024];

// ---------------------------------------------------------------------------
// Helpers
// ---------------------------------------------------------------------------
__device__ __forceinline__ uint32_t smem_to_u32(const void* p) {
    uint32_t a;
    asm("{ .reg .u64 t; cvta.to.shared.u64 t, %1; cvt.u32.u64 %0, t; }"
        : "=r"(a) : "l"(p));
    return a;
}

__device__ __forceinline__ void ldmatrix_x4(uint32_t* r, uint32_t addr) {
    asm volatile(
        "ldmatrix.sync.aligned.m8n8.x4.shared.b16 {%0, %1, %2, %3}, [%4];"
        : "=r"(r[0]), "=r"(r[1]), "=r"(r[2]), "=r"(r[3]) : "r"(addr));
}

__device__ __forceinline__ void ldmatrix_x4_trans(uint32_t* r, uint32_t addr) {
    asm volatile(
        "ldmatrix.sync.aligned.m8n8.x4.trans.shared.b16 {%0, %1, %2, %3}, [%4];"
        : "=r"(r[0]), "=r"(r[1]), "=r"(r[2]), "=r"(r[3]) : "r"(addr));
}

__device__ __forceinline__ void mma_bf16(float* d, const uint32_t* a,
                                         uint32_t b0, uint32_t b1) {
    asm volatile(
        "mma.sync.aligned.m16n8k16.row.col.f32.bf16.bf16.f32 "
        "{%0, %1, %2, %3}, {%4, %5, %6, %7}, {%8, %9}, {%0, %1, %2, %3};"
        : "+f"(d[0]), "+f"(d[1]), "+f"(d[2]), "+f"(d[3])
        : "r"(a[0]), "r"(a[1]), "r"(a[2]), "r"(a[3]), "r"(b0), "r"(b1));
}

__device__ __forceinline__ uint32_t pack2(__nv_bfloat16 a, __nv_bfloat16 b) {
    __nv_bfloat162 t = __halves2bfloat162(a, b);
    return *reinterpret_cast<uint32_t*>(&t);
}

__device__ __forceinline__ uint32_t pack_bf16f(float a, float b) {
    return pack2(__float2bfloat16(a), __float2bfloat16(b));
}

// write hi(x),hi(y) to hi and residuals to lo (2 contiguous bf16 each)
__device__ __forceinline__ void split2_store(float x, float y,
                                             __nv_bfloat16* hi, __nv_bfloat16* lo) {
    __nv_bfloat16 hx = __float2bfloat16(x), hy = __float2bfloat16(y);
    *(__nv_bfloat162*)hi = __halves2bfloat162(hx, hy);
    *(__nv_bfloat162*)lo = __halves2bfloat162(
        __float2bfloat16(x - __bfloat162float(hx)),
        __float2bfloat16(y - __bfloat162float(hy)));
}

// ---------------------------------------------------------------------------
// Precision-split conversion: x -> hi = bf16(x), lo = bf16(x - hi)
// ---------------------------------------------------------------------------
__global__ void split_f32_bf16(const float* __restrict__ x,
                               __nv_bfloat16* __restrict__ hi,
                               __nv_bfloat16* __restrict__ lo, int n4) {
    int i = blockIdx.x * 256 + threadIdx.x;
    if (i >= n4) return;
    float4 v = ((const float4*)x)[i];
    __nv_bfloat16 h0 = __float2bfloat16(v.x), h1 = __float2bfloat16(v.y);
    __nv_bfloat16 h2 = __float2bfloat16(v.z), h3 = __float2bfloat16(v.w);
    __nv_bfloat16 l0 = __float2bfloat16(v.x - __bfloat162float(h0));
    __nv_bfloat16 l1 = __float2bfloat16(v.y - __bfloat162float(h1));
    __nv_bfloat16 l2 = __float2bfloat16(v.z - __bfloat162float(h2));
    __nv_bfloat16 l3 = __float2bfloat16(v.w - __bfloat162float(h3));
    ((__nv_bfloat162*)hi)[2 * i + 0] = __halves2bfloat162(h0, h1);
    ((__nv_bfloat162*)hi)[2 * i + 1] = __halves2bfloat162(h2, h3);
    ((__nv_bfloat162*)lo)[2 * i + 0] = __halves2bfloat162(l0, l1);
    ((__nv_bfloat162*)lo)[2 * i + 1] = __halves2bfloat162(l2, l3);
}

// Build W_all^T (1152 x 1024) split into hi/lo.
__global__ void build_wall_t(const float* __restrict__ Wq,
                             const float* __restrict__ Wk,
                             const float* __restrict__ Wv,
                             __nv_bfloat16* __restrict__ hi,
                             __nv_bfloat16* __restrict__ lo) {
    int i = blockIdx.x * 256 + threadIdx.x;
    if (i >= 1152 * 1024) return;
    int n = i >> 10;
    int k = i & 1023;
    float v;
    if (n < 1024)      v = Wq[k * 1024 + n];
    else if (n < 1088) v = Wk[k * 64 + (n - 1024)];
    else               v = Wv[k * 64 + (n - 1088)];
    __nv_bfloat16 h = __float2bfloat16(v);
    hi[i] = h;
    lo[i] = __float2bfloat16(v - __bfloat162float(h));
}

// Wo^T (1024 x 1024) split into hi/lo
__global__ void build_wo_t(const float* __restrict__ Wo,
                           __nv_bfloat16* __restrict__ hi,
                           __nv_bfloat16* __restrict__ lo) {
    int i = blockIdx.x * 256 + threadIdx.x;
    if (i >= 1024 * 1024) return;
    int n = i >> 10;
    int k = i & 1023;
    float v = Wo[k * 1024 + n];
    __nv_bfloat16 h = __float2bfloat16(v);
    hi[i] = h;
    lo[i] = __float2bfloat16(v - __bfloat162float(h));
}

// ---------------------------------------------------------------------------
// HMMA GEMM (mma.sync m16n8k16 bf16, split precision x3)
// ---------------------------------------------------------------------------
#define LDT 40

__global__ __launch_bounds__(256, 2)
void hmma_gemm(const __nv_bfloat16* __restrict__ Ahi, const __nv_bfloat16* __restrict__ Alo,
               const __nv_bfloat16* __restrict__ Bhi, const __nv_bfloat16* __restrict__ Blo,
               float* __restrict__ C, const float* __restrict__ bias,
               int K, int ldc) {
    __shared__ __nv_bfloat16 sAhi[128 * LDT];
    __shared__ __nv_bfloat16 sAlo[128 * LDT];
    __shared__ __nv_bfloat16 sBhi[128 * LDT];
    __shared__ __nv_bfloat16 sBlo[128 * LDT];

    const int tid  = threadIdx.x;
    const int lane = tid & 31;
    const int wid  = tid >> 5;
    const int warp_row = wid & 3;
    const int warp_col = wid >> 2;

    const int cRow = blockIdx.y * 128;
    const int cCol = blockIdx.x * 128;

    const int lrow = tid >> 1;
    const int seg  = (tid & 1) * 16;
    const __nv_bfloat16* gAhi = Ahi + (size_t)(cRow + lrow) * K + seg;
    const __nv_bfloat16* gAlo = Alo + (size_t)(cRow + lrow) * K + seg;
    const __nv_bfloat16* gBhi = Bhi + (size_t)(cCol + lrow) * K + seg;
    const __nv_bfloat16* gBlo = Blo + (size_t)(cCol + lrow) * K + seg;
    __nv_bfloat16* stA_hi = &sAhi[lrow * LDT + seg];
    __nv_bfloat16* stA_lo = &sAlo[lrow * LDT + seg];
    __nv_bfloat16* stB_hi = &sBhi[lrow * LDT + seg];
    __nv_bfloat16* stB_lo = &sBlo[lrow * LDT + seg];

    const uint32_t aoff =
        ((uint32_t)(warp_row * 32 + (lane & 15)) * LDT + ((lane >> 4) << 3)) * 2;
    const uint32_t boff =
        ((uint32_t)(warp_col * 64 + (lane & 7) + ((lane >> 4) << 3)) * LDT +
         (((lane >> 3) & 1) << 3)) * 2;

    const uint32_t sAhi_b = smem_to_u32(sAhi), sAlo_b = smem_to_u32(sAlo);
    const uint32_t sBhi_b = smem_to_u32(sBhi), sBlo_b = smem_to_u32(sBlo);

    float acc[2][8][4];
#pragma unroll
    for (int mi = 0; mi < 2; mi++)
#pragma unroll
        for (int ni = 0; ni < 8; ni++)
#pragma unroll
            for (int j = 0; j < 4; j++) acc[mi][ni][j] = 0.0f;

    for (int k0 = 0; k0 < K; k0 += 32) {
        *(uint4*)(stA_hi)     = *(const uint4*)(gAhi + k0);
        *(uint4*)(stA_hi + 8) = *(const uint4*)(gAhi + k0 + 8);
        *(uint4*)(stA_lo)     = *(const uint4*)(gAlo + k0);
        *(uint4*)(stA_lo + 8) = *(const uint4*)(gAlo + k0 + 8);
        *(uint4*)(stB_hi)     = *(const uint4*)(gBhi + k0);
        *(uint4*)(stB_hi + 8) = *(const uint4*)(gBhi + k0 + 8);
        *(uint4*)(stB_lo)     = *(const uint4*)(gBlo + k0);
        *(uint4*)(stB_lo + 8) = *(const uint4*)(gBlo + k0 + 8);
        __syncthreads();

#pragma unroll
        for (int ks = 0; ks < 2; ks++) {
            uint32_t ahi[2][4], alo[2][4];
#pragma unroll
            for (int mi = 0; mi < 2; mi++) {
                const uint32_t o = aoff + (uint32_t)(mi * 16 * LDT + ks * 16) * 2;
                ldmatrix_x4(ahi[mi], sAhi_b + o);
                ldmatrix_x4(alo[mi], sAlo_b + o);
            }
#pragma unroll
            for (int g = 0; g < 4; g++) {
                uint32_t bhi[4], blo[4];
                const uint32_t o = boff + (uint32_t)(g * 16 * LDT + ks * 16) * 2;
                ldmatrix_x4(bhi, sBhi_b + o);
                ldmatrix_x4(blo, sBlo_b + o);
#pragma unroll
                for (int mi = 0; mi < 2; mi++) {
                    mma_bf16(acc[mi][2 * g + 0], ahi[mi], bhi[0], bhi[1]);
                    mma_bf16(acc[mi][2 * g + 0], ahi[mi], blo[0], blo[1]);
                    mma_bf16(acc[mi][2 * g + 0], alo[mi], bhi[0], bhi[1]);
                    mma_bf16(acc[mi][2 * g + 1], ahi[mi], bhi[2], bhi[3]);
                    mma_bf16(acc[mi][2 * g + 1], ahi[mi], blo[2], blo[3]);
                    mma_bf16(acc[mi][2 * g + 1], alo[mi], bhi[2], bhi[3]);
                }
            }
        }
        __syncthreads();
    }

#pragma unroll
    for (int mi = 0; mi < 2; mi++) {
        const int row = cRow + warp_row * 32 + mi * 16 + (lane >> 2);
#pragma unroll
        for (int ni = 0; ni < 8; ni++) {
            const int col = cCol + warp_col * 64 + ni * 8 + (lane & 3) * 2;
            float2 v0 = make_float2(acc[mi][ni][0], acc[mi][ni][1]);
            float2 v1 = make_float2(acc[mi][ni][2], acc[mi][ni][3]);
            if (bias != nullptr) {
                float2 bb = *(const float2*)&bias[col];
                v0.x += bb.x; v0.y += bb.y;
                v1.x += bb.x; v1.y += bb.y;
            }
            *(float2*)&C[(size_t)row * ldc + col]       = v0;
            *(float2*)&C[(size_t)(row + 8) * ldc + col] = v1;
        }
    }
}

// ---------------------------------------------------------------------------
// HMMA causal flash-attention (MQA).
// Block = (128-row Q tile, h, b); 8 warps, warp w owns rows w*16..w*16+15.
// SMEM (36 KB) is reused: phase A = Q hi/lo staging [128 x 72]; then per
// KV tile = K hi/lo + V hi/lo [64 x 72] each.
// S = Q.K^T via bf16x3 MMA; online softmax in registers; P.V via bf16x3 MMA
// with V's B-fragments loaded by ldmatrix.trans.
// ---------------------------------------------------------------------------
#define LDA 72

__global__ __launch_bounds__(256, 1)
void attn_hmma(const float* __restrict__ QKV, float* __restrict__ Z) {
    __shared__ __nv_bfloat16 sm[18432];  // 36,864 bytes
    const int tid  = threadIdx.x;
    const int lane = tid & 31;
    const int w    = tid >> 5;
    const int qb = blockIdx.x, h = blockIdx.y, b = blockIdx.z;
    const int qbase = qb * 128;
    const uint32_t smb = smem_to_u32(sm);

    // ---- Phase A: stage Q (scaled by 1/8, exact in bf16) into hi/lo ----
    {
        const int row = tid >> 1, seg = (tid & 1) * 32;
        const float* src = QKV + ((size_t)(b * 2048 + qbase + row)) * 1152 + h * 64 + seg;
        __nv_bfloat16* dhi = sm + row * LDA + seg;
        __nv_bfloat16* dlo = dhi + 9216;
#pragma unroll
        for (int c = 0; c < 8; c++) {
            float4 v = ((const float4*)src)[c];
            v.x *= 0.125f; v.y *= 0.125f; v.z *= 0.125f; v.w *= 0.125f;
            split2_store(v.x, v.y, dhi + c * 4,     dlo + c * 4);
            split2_store(v.z, v.w, dhi + c * 4 + 2, dlo + c * 4 + 2);
        }
    }
    __syncthreads();

    // Q fragments: qhi/qlo[kc][4], kc = k16 step over D=64
    uint32_t qhi[4][4], qlo[4][4];
    {
        const uint32_t aoff = ((uint32_t)(w * 16 + (lane & 15)) * LDA + ((lane >> 4) << 3)) * 2;
#pragma unroll
        for (int kc = 0; kc < 4; kc++) {
            ldmatrix_x4(qhi[kc], smb + aoff + kc * 32);
            ldmatrix_x4(qlo[kc], smb + 18432 + aoff + kc * 32);
        }
    }
    __syncthreads();  // SMEM now free for K/V tiles

    float acc_o[8][4];
#pragma unroll
    for (int i = 0; i < 8; i++)
#pragma unroll
        for (int j = 0; j < 4; j++) acc_o[i][j] = 0.0f;
    float m0 = -1e30f, m1 = -1e30f, l0 = 0.0f, l1 = 0.0f;

    const int r0    = lane >> 2;
    const int g0    = qbase + w * 16 + r0;     // global query row (g1 = g0 + 8)
    const int colq  = (lane & 3) * 2;
    const int rmaxw = qbase + w * 16 + 15;

    // ldmatrix lane offsets
    const uint32_t koffb = ((uint32_t)((lane & 7) + ((lane >> 4) << 3)) * LDA +
                           (((lane >> 3) & 1) << 3)) * 2;
    const uint32_t mi4   = lane >> 3;
    const uint32_t voffb = ((uint32_t)((mi4 & 1) * 8 + (lane & 7)) * LDA +
                           ((mi4 >> 1) << 3)) * 2;

    const int nkv = 2 * (qb + 1);
    for (int kvt = 0; kvt < nkv; kvt++) {
        // ---- load K/V tile (64 x 64 each), split hi/lo ----
        {
            const int row = tid >> 2, seg = (tid & 3) * 16;
            const float* src = QKV + ((size_t)(b * 2048 + kvt * 64 + row)) * 1152 + 1024 + seg;
            __nv_bfloat16* base = sm + row * LDA + seg;
#pragma unroll
            for (int c = 0; c < 4; c++) {
                float4 kv = ((const float4*)src)[c];
                split2_store(kv.x, kv.y, base + c * 4,     base + 4608 + c * 4);
                split2_store(kv.z, kv.w, base + c * 4 + 2, base + 4608 + c * 4 + 2);
                float4 vv = ((const float4*)(src + 64))[c];
                split2_store(vv.x, vv.y, base + 9216 + c * 4,     base + 13824 + c * 4);
                split2_store(vv.z, vv.w, base + 9216 + c * 4 + 2, base + 13824 + c * 4 + 2);
            }
        }
        __syncthreads();

        if (kvt * 64 <= rmaxw) {
            // ---- S = Q . K^T (bf16 x3) ----
            float s[8][4];
#pragma unroll
            for (int i = 0; i < 8; i++)
#pragma unroll
                for (int j = 0; j < 4; j++) s[i][j] = 0.0f;
#pragma unroll
            for (int kc = 0; kc < 4; kc++) {
#pragma unroll
                for (int nbp = 0; nbp < 4; nbp++) {
                    uint32_t khi[4], klo[4];
                    const uint32_t off = koffb + (uint32_t)(nbp * 16 * LDA + kc * 16) * 2;
                    ldmatrix_x4(khi, smb + off);
                    ldmatrix_x4(klo, smb + 9216 + off);
                    mma_bf16(s[2 * nbp],     qhi[kc], khi[0], khi[1]);
                    mma_bf16(s[2 * nbp],     qhi[kc], klo[0], klo[1]);
                    mma_bf16(s[2 * nbp],     qlo[kc], khi[0], khi[1]);
                    mma_bf16(s[2 * nbp + 1], qhi[kc], khi[2], khi[3]);
                    mma_bf16(s[2 * nbp + 1], qhi[kc], klo[2], klo[3]);
                    mma_bf16(s[2 * nbp + 1], qlo[kc], khi[2], khi[3]);
                }
            }
            // ---- causal mask (diagonal tiles only) ----
            if (kvt >= 2 * qb) {
                const int jb = kvt * 64 + colq;
#pragma unroll
                for (int ni = 0; ni < 8; ni++) {
                    const int j0 = jb + ni * 8;
                    if (j0     > g0)     s[ni][0] = -1e30f;
                    if (j0 + 1 > g0)     s[ni][1] = -1e30f;
                    if (j0     > g0 + 8) s[ni][2] = -1e30f;
                    if (j0 + 1 > g0 + 8) s[ni][3] = -1e30f;
                }
            }
            // ---- online softmax ----
            float mt0 = -1e30f, mt1 = -1e30f;
#pragma unroll
            for (int ni = 0; ni < 8; ni++) {
                mt0 = fmaxf(mt0, fmaxf(s[ni][0], s[ni][1]));
                mt1 = fmaxf(mt1, fmaxf(s[ni][2], s[ni][3]));
            }
            mt0 = fmaxf(mt0, __shfl_xor_sync(0xffffffffu, mt0, 1));
            mt0 = fmaxf(mt0, __shfl_xor_sync(0xffffffffu, mt0, 2));
            mt1 = fmaxf(mt1, __shfl_xor_sync(0xffffffffu, mt1, 1));
            mt1 = fmaxf(mt1, __shfl_xor_sync(0xffffffffu, mt1, 2));
            const float m0n = fmaxf(fmaxf(m0, mt0), -1e20f);
            const float m1n = fmaxf(fmaxf(m1, mt1), -1e20f);
            const float a0 = __expf(m0 - m0n), a1 = __expf(m1 - m1n);
            l0 *= a0; l1 *= a1;
#pragma unroll
            for (int ni = 0; ni < 8; ni++) {
                acc_o[ni][0] *= a0; acc_o[ni][1] *= a0;
                acc_o[ni][2] *= a1; acc_o[ni][3] *= a1;
            }
            m0 = m0n; m1 = m1n;

            // P = exp(S - m): split hi/lo, build A fragments per k16 step
            uint32_t pahi[4][4], palo[4][4];
#pragma unroll
            for (int ni = 0; ni < 8; ni++) {
                const float p0 = __expf(s[ni][0] - m0n);
                const float p1 = __expf(s[ni][1] - m0n);
                const float p2 = __expf(s[ni][2] - m1n);
                const float p3 = __expf(s[ni][3] - m1n);
                l0 += p0 + p1; l1 += p2 + p3;
                const int kc = ni >> 1;
                const int o  = (ni & 1) * 2;
                const __nv_bfloat16 h0 = __float2bfloat16(p0);
                const __nv_bfloat16 h1 = __float2bfloat16(p1);
                const __nv_bfloat16 h2 = __float2bfloat16(p2);
                const __nv_bfloat16 h3 = __float2bfloat16(p3);
                pahi[kc][o]     = pack2(h0, h1);
                pahi[kc][o + 1] = pack2(h2, h3);
                palo[kc][o]     = pack_bf16f(p0 - __bfloat162float(h0),
                                             p1 - __bfloat162float(h1));
                palo[kc][o + 1] = pack_bf16f(p2 - __bfloat162float(h2),
                                             p3 - __bfloat162float(h3));
            }

            // ---- O += P . V (bf16 x3), V B-fragments via ldmatrix.trans ----
#pragma unroll
            for (int kc = 0; kc < 4; kc++) {
#pragma unroll
                for (int nb = 0; nb < 4; nb++) {
                    uint32_t vhi[4], vlo[4];
                    const uint32_t off = voffb + (uint32_t)(kc * 16 * LDA + nb * 16) * 2;
                    ldmatrix_x4_trans(vhi, smb + 18432 + off);
                    ldmatrix_x4_trans(vlo, smb + 27648 + off);
                    mma_bf16(acc_o[2 * nb],     pahi[kc], vhi[0], vhi[1]);
                    mma_bf16(acc_o[2 * nb],     pahi[kc], vlo[0], vlo[1]);
                    mma_bf16(acc_o[2 * nb],     palo[kc], vhi[0], vhi[1]);
                    mma_bf16(acc_o[2 * nb + 1], pahi[kc], vhi[2], vhi[3]);
                    mma_bf16(acc_o[2 * nb + 1], pahi[kc], vlo[2], vlo[3]);
                    mma_bf16(acc_o[2 * nb + 1], palo[kc], vhi[2], vhi[3]);
                }
            }
        }
        __syncthreads();
    }

    // ---- finalize: reduce l over quad, normalize, store ----
    l0 += __shfl_xor_sync(0xffffffffu, l0, 1);
    l0 += __shfl_xor_sync(0xffffffffu, l0, 2);
    l1 += __shfl_xor_sync(0xffffffffu, l1, 1);
    l1 += __shfl_xor_sync(0xffffffffu, l1, 2);
    const float inv0 = 1.0f / l0, inv1 = 1.0f / l1;
    const float* z0src;
    float* z0 = Z + ((size_t)(b * 2048 + g0)) * 1024 + h * 64 + colq;
    float* z1 = z0 + (size_t)8 * 1024;
#pragma unroll
    for (int ni = 0; ni < 8; ni++) {
        *(float2*)(z0 + ni * 8) = make_float2(acc_o[ni][0] * inv0, acc_o[ni][1] * inv0);
        *(float2*)(z1 + ni * 8) = make_float2(acc_o[ni][2] * inv1, acc_o[ni][3] * inv1);
    }
}

// ---------------------------------------------------------------------------
// Launch
// ---------------------------------------------------------------------------
extern "C" void kernel_launch(void* const* d_in, const int* in_sizes, int n_in,
                              void* d_out, int out_size) {
    const float* x  = (const float*)d_in[0];  // (2,2048,1024)
    const float* Wq = (const float*)d_in[1];  // (1024,1024)
    const float* Wk = (const float*)d_in[2];  // (1024,64)
    const float* Wv = (const float*)d_in[3];  // (1024,64)
    const float* Wo = (const float*)d_in[4];  // (1024,1024)
    const float* bo = (const float*)d_in[5];  // (1024,)

    float *QKVp, *Zp;
    __nv_bfloat16 *Xhi, *Xlo, *Wthi, *Wtlo, *Wothi, *Wotlo, *Zhi, *Zlo;
    cudaGetSymbolAddress((void**)&QKVp,  g_QKV);
    cudaGetSymbolAddress((void**)&Zp,    g_Z);
    cudaGetSymbolAddress((void**)&Xhi,   g_Xhi);
    cudaGetSymbolAddress((void**)&Xlo,   g_Xlo);
    cudaGetSymbolAddress((void**)&Wthi,  g_Wthi);
    cudaGetSymbolAddress((void**)&Wtlo,  g_Wtlo);
    cudaGetSymbolAddress((void**)&Wothi, g_Wothi);
    cudaGetSymbolAddress((void**)&Wotlo, g_Wotlo);
    cudaGetSymbolAddress((void**)&Zhi,   g_Zhi);
    cudaGetSymbolAddress((void**)&Zlo,   g_Zlo);

    // 1) precision-split inputs / weights
    split_f32_bf16<<<CDIV(4096 * 1024 / 4, 256), 256>>>(x, Xhi, Xlo, 4096 * 1024 / 4);
    build_wall_t<<<CDIV(1152 * 1024, 256), 256>>>(Wq, Wk, Wv, Wthi, Wtlo);
    build_wo_t<<<CDIV(1024 * 1024, 256), 256>>>(Wo, Wothi, Wotlo);

    // 2) QKV = X @ [Wq|Wk|Wv]   (4096 x 1152, K = 1024) on HMMA
    hmma_gemm<<<dim3(1152 / 128, 4096 / 128), 256>>>(
        Xhi, Xlo, Wthi, Wtlo, QKVp, nullptr, 1024, 1152);

    // 3) causal flash-attention MQA on HMMA
    attn_hmma<<<dim3(16, 16, 2), 256>>>(QKVp, Zp);

    // 4) split Z, then out = Z @ Wo + bo -> d_out on HMMA
    split_f32_bf16<<<CDIV(4096 * 1024 / 4, 256), 256>>>(Zp, Zhi, Zlo, 4096 * 1024 / 4);
    hmma_gemm<<<dim3(1024 / 128, 4096 / 128), 256>>>(
        Zhi, Zlo, Wothi, Wotlo, (float*)d_out, bo, 1024, 1024);
}

// round 15
// speedup vs baseline: 4.3682x; 1.1564x over previous
#include <cuda_runtime.h>
#include <cuda_bf16.h>
#include <cstdint>

// Problem constants: B=2, N=2048, E=1024, H=16, D=64
// M = B*N = 4096 flattened rows. QKV fused width = 1024 + 64 + 64 = 1152.

#define CDIV(a, b) (((a) + (b) - 1) / (b))

// ---------------------------------------------------------------------------
// Scratch (__device__ globals; allocation-free rule)
// ---------------------------------------------------------------------------
__device__ __nv_bfloat16   g_QKVhi[4096 * 1152];  // [Q|K|V] hi, Q pre-scaled by 1/8
__device__ __nv_bfloat16   g_QKVlo[4096 * 1152];
__device__ __nv_bfloat16   g_Xhi[4096 * 1024];
__device__ __nv_bfloat16   g_Xlo[4096 * 1024];
__device__ __nv_bfloat16   g_Wthi[1152 * 1024];  // [Wq/8|Wk|Wv]^T (N-major, K contig)
__device__ __nv_bfloat16   g_Wtlo[1152 * 1024];
__device__ __nv_bfloat16   g_Wothi[1024 * 1024]; // Wo^T
__device__ __nv_bfloat16   g_Wotlo[1024 * 1024];
__device__ __nv_bfloat16   g_Zhi[4096 * 1024];   // attention output, split
__device__ __nv_bfloat16   g_Zlo[4096 * 1024];

// ---------------------------------------------------------------------------
// Helpers
// ---------------------------------------------------------------------------
__device__ __forceinline__ uint32_t smem_to_u32(const void* p) {
    uint32_t a;
    asm("{ .reg .u64 t; cvta.to.shared.u64 t, %1; cvt.u32.u64 %0, t; }"
        : "=r"(a) : "l"(p));
    return a;
}

__device__ __forceinline__ void ldmatrix_x4(uint32_t* r, uint32_t addr) {
    asm volatile(
        "ldmatrix.sync.aligned.m8n8.x4.shared.b16 {%0, %1, %2, %3}, [%4];"
        : "=r"(r[0]), "=r"(r[1]), "=r"(r[2]), "=r"(r[3]) : "r"(addr));
}

__device__ __forceinline__ void ldmatrix_x4_trans(uint32_t* r, uint32_t addr) {
    asm volatile(
        "ldmatrix.sync.aligned.m8n8.x4.trans.shared.b16 {%0, %1, %2, %3}, [%4];"
        : "=r"(r[0]), "=r"(r[1]), "=r"(r[2]), "=r"(r[3]) : "r"(addr));
}

__device__ __forceinline__ void mma_bf16(float* d, const uint32_t* a,
                                         uint32_t b0, uint32_t b1) {
    asm volatile(
        "mma.sync.aligned.m16n8k16.row.col.f32.bf16.bf16.f32 "
        "{%0, %1, %2, %3}, {%4, %5, %6, %7}, {%8, %9}, {%0, %1, %2, %3};"
        : "+f"(d[0]), "+f"(d[1]), "+f"(d[2]), "+f"(d[3])
        : "r"(a[0]), "r"(a[1]), "r"(a[2]), "r"(a[3]), "r"(b0), "r"(b1));
}

__device__ __forceinline__ uint32_t pack2(__nv_bfloat16 a, __nv_bfloat16 b) {
    __nv_bfloat162 t = __halves2bfloat162(a, b);
    return *reinterpret_cast<uint32_t*>(&t);
}

__device__ __forceinline__ uint32_t pack_bf16f(float a, float b) {
    return pack2(__float2bfloat16(a), __float2bfloat16(b));
}

// write hi(x),hi(y) to hi and residuals to lo (2 contiguous bf16 each)
__device__ __forceinline__ void split2_store(float x, float y,
                                             __nv_bfloat16* hi, __nv_bfloat16* lo) {
    __nv_bfloat16 hx = __float2bfloat16(x), hy = __float2bfloat16(y);
    *(__nv_bfloat162*)hi = __halves2bfloat162(hx, hy);
    *(__nv_bfloat162*)lo = __halves2bfloat162(
        __float2bfloat16(x - __bfloat162float(hx)),
        __float2bfloat16(y - __bfloat162float(hy)));
}

#define CP_ASYNC16(dst_u32, src_ptr)                                           \
    asm volatile("cp.async.cg.shared.global [%0], [%1], 16;"                   \
                 :: "r"(dst_u32), "l"(src_ptr))
#define CP_COMMIT()  asm volatile("cp.async.commit_group;" ::: "memory")
#define CP_WAIT1()   asm volatile("cp.async.wait_group 1;" ::: "memory")
#define CP_WAIT0()   asm volatile("cp.async.wait_group 0;" ::: "memory")

// ---------------------------------------------------------------------------
// Precision-split conversion: x -> hi = bf16(x), lo = bf16(x - hi)
// ---------------------------------------------------------------------------
__global__ void split_f32_bf16(const float* __restrict__ x,
                               __nv_bfloat16* __restrict__ hi,
                               __nv_bfloat16* __restrict__ lo, int n4) {
    int i = blockIdx.x * 256 + threadIdx.x;
    if (i >= n4) return;
    float4 v = ((const float4*)x)[i];
    __nv_bfloat16 h0 = __float2bfloat16(v.x), h1 = __float2bfloat16(v.y);
    __nv_bfloat16 h2 = __float2bfloat16(v.z), h3 = __float2bfloat16(v.w);
    __nv_bfloat16 l0 = __float2bfloat16(v.x - __bfloat162float(h0));
    __nv_bfloat16 l1 = __float2bfloat16(v.y - __bfloat162float(h1));
    __nv_bfloat16 l2 = __float2bfloat16(v.z - __bfloat162float(h2));
    __nv_bfloat16 l3 = __float2bfloat16(v.w - __bfloat162float(h3));
    ((__nv_bfloat162*)hi)[2 * i + 0] = __halves2bfloat162(h0, h1);
    ((__nv_bfloat162*)hi)[2 * i + 1] = __halves2bfloat162(h2, h3);
    ((__nv_bfloat162*)lo)[2 * i + 0] = __halves2bfloat162(l0, l1);
    ((__nv_bfloat162*)lo)[2 * i + 1] = __halves2bfloat162(l2, l3);
}

// Build W_all^T (1152 x 1024) split into hi/lo. Wq columns pre-scaled by 1/8
// (exact power of two, equivalent to scaling scores by 1/sqrt(D)).
__global__ void build_wall_t(const float* __restrict__ Wq,
                             const float* __restrict__ Wk,
                             const float* __restrict__ Wv,
                             __nv_bfloat16* __restrict__ hi,
                             __nv_bfloat16* __restrict__ lo) {
    int i = blockIdx.x * 256 + threadIdx.x;
    if (i >= 1152 * 1024) return;
    int n = i >> 10;
    int k = i & 1023;
    float v;
    if (n < 1024)      v = Wq[k * 1024 + n] * 0.125f;
    else if (n < 1088) v = Wk[k * 64 + (n - 1024)];
    else               v = Wv[k * 64 + (n - 1088)];
    __nv_bfloat16 h = __float2bfloat16(v);
    hi[i] = h;
    lo[i] = __float2bfloat16(v - __bfloat162float(h));
}

// Wo^T (1024 x 1024) split into hi/lo
__global__ void build_wo_t(const float* __restrict__ Wo,
                           __nv_bfloat16* __restrict__ hi,
                           __nv_bfloat16* __restrict__ lo) {
    int i = blockIdx.x * 256 + threadIdx.x;
    if (i >= 1024 * 1024) return;
    int n = i >> 10;
    int k = i & 1023;
    float v = Wo[k * 1024 + n];
    __nv_bfloat16 h = __float2bfloat16(v);
    hi[i] = h;
    lo[i] = __float2bfloat16(v - __bfloat162float(h));
}

// ---------------------------------------------------------------------------
// HMMA GEMM (mma.sync m16n8k16 bf16, split precision x3), cp.async
// double-buffered. Dynamic SMEM: 2 stages x 4 tiles x 128 x LDT bf16 = 80 KB.
// SPLIT_OUT: write hi/lo bf16 (Chi/Clo); else fp32 C (+bias).
// ---------------------------------------------------------------------------
#define LDT 40
#define TILE_BYTES  (128 * LDT * 2)      // 10240
#define STAGE_BYTES (4 * TILE_BYTES)     // 40960
#define GEMM_DSMEM  (2 * STAGE_BYTES)    // 81920

template <bool SPLIT_OUT>
__global__ __launch_bounds__(256, 2)
void hmma_gemm(const __nv_bfloat16* __restrict__ Ahi, const __nv_bfloat16* __restrict__ Alo,
               const __nv_bfloat16* __restrict__ Bhi, const __nv_bfloat16* __restrict__ Blo,
               float* __restrict__ C, const float* __restrict__ bias,
               __nv_bfloat16* __restrict__ Chi, __nv_bfloat16* __restrict__ Clo,
               int K, int ldc) {
    extern __shared__ __nv_bfloat16 dsm[];
    const uint32_t smb = smem_to_u32(dsm);

    const int tid  = threadIdx.x;
    const int lane = tid & 31;
    const int wid  = tid >> 5;
    const int warp_row = wid & 3;
    const int warp_col = wid >> 2;
    const int cRow = blockIdx.y * 128;
    const int cCol = blockIdx.x * 128;

    // loader: row = tid>>1 (0..127), seg = (tid&1)*16 bf16 (2 x 16B cp.async)
    const int lrow = tid >> 1;
    const int seg  = (tid & 1) * 16;
    const __nv_bfloat16* gsrc[4];
    gsrc[0] = Ahi + (size_t)(cRow + lrow) * K + seg;
    gsrc[1] = Alo + (size_t)(cRow + lrow) * K + seg;
    gsrc[2] = Bhi + (size_t)(cCol + lrow) * K + seg;
    gsrc[3] = Blo + (size_t)(cCol + lrow) * K + seg;
    const uint32_t st_off = (uint32_t)(lrow * LDT + seg) * 2;

    const uint32_t aoff =
        ((uint32_t)(warp_row * 32 + (lane & 15)) * LDT + ((lane >> 4) << 3)) * 2;
    const uint32_t boff =
        ((uint32_t)(warp_col * 64 + (lane & 7) + ((lane >> 4) << 3)) * LDT +
         (((lane >> 3) & 1) << 3)) * 2;

    float acc[2][8][4];
#pragma unroll
    for (int mi = 0; mi < 2; mi++)
#pragma unroll
        for (int ni = 0; ni < 8; ni++)
#pragma unroll
            for (int j = 0; j < 4; j++) acc[mi][ni][j] = 0.0f;

    const int nch = K >> 5;  // chunks of 32

    // prologue: stream chunk 0 into stage 0
#pragma unroll
    for (int t = 0; t < 4; t++) {
        const uint32_t d = smb + t * TILE_BYTES + st_off;
        CP_ASYNC16(d,      gsrc[t]);
        CP_ASYNC16(d + 16, gsrc[t] + 8);
    }
    CP_COMMIT();

    for (int ch = 0; ch < nch; ch++) {
        if (ch + 1 < nch) {
            const uint32_t sb = smb + ((ch + 1) & 1) * STAGE_BYTES;
            const int k0 = (ch + 1) * 32;
#pragma unroll
            for (int t = 0; t < 4; t++) {
                const uint32_t d = sb + t * TILE_BYTES + st_off;
                CP_ASYNC16(d,      gsrc[t] + k0);
                CP_ASYNC16(d + 16, gsrc[t] + k0 + 8);
            }
            CP_COMMIT();
            CP_WAIT1();
        } else {
            CP_WAIT0();
        }
        __syncthreads();

        const uint32_t sb = smb + (ch & 1) * STAGE_BYTES;
#pragma unroll
        for (int ks = 0; ks < 2; ks++) {
            uint32_t ahi[2][4], alo[2][4];
#pragma unroll
            for (int mi = 0; mi < 2; mi++) {
                const uint32_t o = aoff + (uint32_t)(mi * 16 * LDT) * 2 + ks * 32;
                ldmatrix_x4(ahi[mi], sb + o);
                ldmatrix_x4(alo[mi], sb + TILE_BYTES + o);
            }
#pragma unroll
            for (int g = 0; g < 4; g++) {
                uint32_t bhi[4], blo[4];
                const uint32_t o = boff + (uint32_t)(g * 16 * LDT) * 2 + ks * 32;
                ldmatrix_x4(bhi, sb + 2 * TILE_BYTES + o);
                ldmatrix_x4(blo, sb + 3 * TILE_BYTES + o);
#pragma unroll
                for (int mi = 0; mi < 2; mi++) {
                    mma_bf16(acc[mi][2 * g + 0], ahi[mi], bhi[0], bhi[1]);
                    mma_bf16(acc[mi][2 * g + 0], ahi[mi], blo[0], blo[1]);
                    mma_bf16(acc[mi][2 * g + 0], alo[mi], bhi[0], bhi[1]);
                    mma_bf16(acc[mi][2 * g + 1], ahi[mi], bhi[2], bhi[3]);
                    mma_bf16(acc[mi][2 * g + 1], ahi[mi], blo[2], blo[3]);
                    mma_bf16(acc[mi][2 * g + 1], alo[mi], bhi[2], bhi[3]);
                }
            }
        }
        __syncthreads();
    }

    // ---- epilogue ----
#pragma unroll
    for (int mi = 0; mi < 2; mi++) {
        const int row = cRow + warp_row * 32 + mi * 16 + (lane >> 2);
#pragma unroll
        for (int ni = 0; ni < 8; ni++) {
            const int col = cCol + warp_col * 64 + ni * 8 + (lane & 3) * 2;
            if (SPLIT_OUT) {
                const size_t i0 = (size_t)row * ldc + col;
                const size_t i1 = (size_t)(row + 8) * ldc + col;
                split2_store(acc[mi][ni][0], acc[mi][ni][1], &Chi[i0], &Clo[i0]);
                split2_store(acc[mi][ni][2], acc[mi][ni][3], &Chi[i1], &Clo[i1]);
            } else {
                float2 v0 = make_float2(acc[mi][ni][0], acc[mi][ni][1]);
                float2 v1 = make_float2(acc[mi][ni][2], acc[mi][ni][3]);
                if (bias != nullptr) {
                    float2 bb = *(const float2*)&bias[col];
                    v0.x += bb.x; v0.y += bb.y;
                    v1.x += bb.x; v1.y += bb.y;
                }
                *(float2*)&C[(size_t)row * ldc + col]       = v0;
                *(float2*)&C[(size_t)(row + 8) * ldc + col] = v1;
            }
        }
    }
}

// ---------------------------------------------------------------------------
// HMMA causal flash-attention (MQA), bf16 hi/lo QKV input, bf16 hi/lo Z out.
// Block = (128-row Q tile, h, b); 8 warps, warp w owns rows w*16..w*16+15.
// SMEM reused: phase A = Q hi/lo [128 x 72]; per KV tile = K hi/lo + V hi/lo.
// ---------------------------------------------------------------------------
#define LDA 72

__global__ __launch_bounds__(256, 1)
void attn_hmma(const __nv_bfloat16* __restrict__ QKVhi,
               const __nv_bfloat16* __restrict__ QKVlo,
               __nv_bfloat16* __restrict__ Zhi,
               __nv_bfloat16* __restrict__ Zlo) {
    __shared__ __nv_bfloat16 sm[18432];  // 36,864 bytes
    const int tid  = threadIdx.x;
    const int lane = tid & 31;
    const int w    = tid >> 5;
    const int qb = blockIdx.x, h = blockIdx.y, b = blockIdx.z;
    const int qbase = qb * 128;
    const uint32_t smb = smem_to_u32(sm);

    // ---- Phase A: copy pre-scaled Q hi/lo (bf16) into SMEM ----
    {
        const int row = tid >> 1, part = (tid & 1) * 32;
        const size_t gidx = ((size_t)(b * 2048 + qbase + row)) * 1152 + h * 64 + part;
        const uint4* qh = (const uint4*)(QKVhi + gidx);
        const uint4* ql = (const uint4*)(QKVlo + gidx);
        uint4* dh = (uint4*)(sm + row * LDA + part);
        uint4* dl = (uint4*)(sm + 9216 + row * LDA + part);
#pragma unroll
        for (int c = 0; c < 4; c++) { dh[c] = qh[c]; dl[c] = ql[c]; }
    }
    __syncthreads();

    // Q fragments: qhi/qlo[kc][4], kc = k16 step over D=64
    uint32_t qhi[4][4], qlo[4][4];
    {
        const uint32_t aoff = ((uint32_t)(w * 16 + (lane & 15)) * LDA + ((lane >> 4) << 3)) * 2;
#pragma unroll
        for (int kc = 0; kc < 4; kc++) {
            ldmatrix_x4(qhi[kc], smb + aoff + kc * 32);
            ldmatrix_x4(qlo[kc], smb + 18432 + aoff + kc * 32);
        }
    }
    __syncthreads();  // SMEM now free for K/V tiles

    float acc_o[8][4];
#pragma unroll
    for (int i = 0; i < 8; i++)
#pragma unroll
        for (int j = 0; j < 4; j++) acc_o[i][j] = 0.0f;
    float m0 = -1e30f, m1 = -1e30f, l0 = 0.0f, l1 = 0.0f;

    const int r0    = lane >> 2;
    const int g0    = qbase + w * 16 + r0;     // global query row (g1 = g0 + 8)
    const int colq  = (lane & 3) * 2;
    const int rmaxw = qbase + w * 16 + 15;

    const uint32_t koffb = ((uint32_t)((lane & 7) + ((lane >> 4) << 3)) * LDA +
                           (((lane >> 3) & 1) << 3)) * 2;
    const uint32_t mi4   = lane >> 3;
    const uint32_t voffb = ((uint32_t)((mi4 & 1) * 8 + (lane & 7)) * LDA +
                           ((mi4 >> 1) << 3)) * 2;

    const int nkv = 2 * (qb + 1);
    for (int kvt = 0; kvt < nkv; kvt++) {
        // ---- copy K/V tile hi/lo (bf16, no conversion work) ----
        {
            const int row = tid >> 2, seg = (tid & 3) * 16;
            const size_t kidx = ((size_t)(b * 2048 + kvt * 64 + row)) * 1152 + 1024 + seg;
            const size_t vidx = kidx + 64;
            const uint4* kh = (const uint4*)(QKVhi + kidx);
            const uint4* kl = (const uint4*)(QKVlo + kidx);
            const uint4* vh = (const uint4*)(QKVhi + vidx);
            const uint4* vl = (const uint4*)(QKVlo + vidx);
            __nv_bfloat16* base = sm + row * LDA + seg;
#pragma unroll
            for (int c = 0; c < 2; c++) {
                ((uint4*)(base))[c]         = kh[c];
                ((uint4*)(base + 4608))[c]  = kl[c];
                ((uint4*)(base + 9216))[c]  = vh[c];
                ((uint4*)(base + 13824))[c] = vl[c];
            }
        }
        __syncthreads();

        if (kvt * 64 <= rmaxw) {
            // ---- S = Q . K^T (bf16 x3) ----
            float s[8][4];
#pragma unroll
            for (int i = 0; i < 8; i++)
#pragma unroll
                for (int j = 0; j < 4; j++) s[i][j] = 0.0f;
#pragma unroll
            for (int kc = 0; kc < 4; kc++) {
#pragma unroll
                for (int nbp = 0; nbp < 4; nbp++) {
                    uint32_t khi[4], klo[4];
                    const uint32_t off = koffb + (uint32_t)(nbp * 16 * LDA + kc * 16) * 2;
                    ldmatrix_x4(khi, smb + off);
                    ldmatrix_x4(klo, smb + 9216 + off);
                    mma_bf16(s[2 * nbp],     qhi[kc], khi[0], khi[1]);
                    mma_bf16(s[2 * nbp],     qhi[kc], klo[0], klo[1]);
                    mma_bf16(s[2 * nbp],     qlo[kc], khi[0], khi[1]);
                    mma_bf16(s[2 * nbp + 1], qhi[kc], khi[2], khi[3]);
                    mma_bf16(s[2 * nbp + 1], qhi[kc], klo[2], klo[3]);
                    mma_bf16(s[2 * nbp + 1], qlo[kc], khi[2], khi[3]);
                }
            }
            // ---- causal mask (diagonal tiles only) ----
            if (kvt >= 2 * qb) {
                const int jb = kvt * 64 + colq;
#pragma unroll
                for (int ni = 0; ni < 8; ni++) {
                    const int j0 = jb + ni * 8;
                    if (j0     > g0)     s[ni][0] = -1e30f;
                    if (j0 + 1 > g0)     s[ni][1] = -1e30f;
                    if (j0     > g0 + 8) s[ni][2] = -1e30f;
                    if (j0 + 1 > g0 + 8) s[ni][3] = -1e30f;
                }
            }
            // ---- online softmax ----
            float mt0 = -1e30f, mt1 = -1e30f;
#pragma unroll
            for (int ni = 0; ni < 8; ni++) {
                mt0 = fmaxf(mt0, fmaxf(s[ni][0], s[ni][1]));
                mt1 = fmaxf(mt1, fmaxf(s[ni][2], s[ni][3]));
            }
            mt0 = fmaxf(mt0, __shfl_xor_sync(0xffffffffu, mt0, 1));
            mt0 = fmaxf(mt0, __shfl_xor_sync(0xffffffffu, mt0, 2));
            mt1 = fmaxf(mt1, __shfl_xor_sync(0xffffffffu, mt1, 1));
            mt1 = fmaxf(mt1, __shfl_xor_sync(0xffffffffu, mt1, 2));
            const float m0n = fmaxf(fmaxf(m0, mt0), -1e20f);
            const float m1n = fmaxf(fmaxf(m1, mt1), -1e20f);
            const float a0 = __expf(m0 - m0n), a1 = __expf(m1 - m1n);
            l0 *= a0; l1 *= a1;
#pragma unroll
            for (int ni = 0; ni < 8; ni++) {
                acc_o[ni][0] *= a0; acc_o[ni][1] *= a0;
                acc_o[ni][2] *= a1; acc_o[ni][3] *= a1;
            }
            m0 = m0n; m1 = m1n;

            // P = exp(S - m): split hi/lo, build A fragments per k16 step
            uint32_t pahi[4][4], palo[4][4];
#pragma unroll
            for (int ni = 0; ni < 8; ni++) {
                const float p0 = __expf(s[ni][0] - m0n);
                const float p1 = __expf(s[ni][1] - m0n);
                const float p2 = __expf(s[ni][2] - m1n);
                const float p3 = __expf(s[ni][3] - m1n);
                l0 += p0 + p1; l1 += p2 + p3;
                const int kc = ni >> 1;
                const int o  = (ni & 1) * 2;
                const __nv_bfloat16 h0 = __float2bfloat16(p0);
                const __nv_bfloat16 h1 = __float2bfloat16(p1);
                const __nv_bfloat16 h2 = __float2bfloat16(p2);
                const __nv_bfloat16 h3 = __float2bfloat16(p3);
                pahi[kc][o]     = pack2(h0, h1);
                pahi[kc][o + 1] = pack2(h2, h3);
                palo[kc][o]     = pack_bf16f(p0 - __bfloat162float(h0),
                                             p1 - __bfloat162float(h1));
                palo[kc][o + 1] = pack_bf16f(p2 - __bfloat162float(h2),
                                             p3 - __bfloat162float(h3));
            }

            // ---- O += P . V (bf16 x3), V B-fragments via ldmatrix.trans ----
#pragma unroll
            for (int kc = 0; kc < 4; kc++) {
#pragma unroll
                for (int nb = 0; nb < 4; nb++) {
                    uint32_t vhi[4], vlo[4];
                    const uint32_t off = voffb + (uint32_t)(kc * 16 * LDA + nb * 16) * 2;
                    ldmatrix_x4_trans(vhi, smb + 18432 + off);
                    ldmatrix_x4_trans(vlo, smb + 27648 + off);
                    mma_bf16(acc_o[2 * nb],     pahi[kc], vhi[0], vhi[1]);
                    mma_bf16(acc_o[2 * nb],     pahi[kc], vlo[0], vlo[1]);
                    mma_bf16(acc_o[2 * nb],     palo[kc], vhi[0], vhi[1]);
                    mma_bf16(acc_o[2 * nb + 1], pahi[kc], vhi[2], vhi[3]);
                    mma_bf16(acc_o[2 * nb + 1], pahi[kc], vlo[2], vlo[3]);
                    mma_bf16(acc_o[2 * nb + 1], palo[kc], vhi[2], vhi[3]);
                }
            }
        }
        __syncthreads();
    }

    // ---- finalize: reduce l over quad, normalize, store split Z ----
    l0 += __shfl_xor_sync(0xffffffffu, l0, 1);
    l0 += __shfl_xor_sync(0xffffffffu, l0, 2);
    l1 += __shfl_xor_sync(0xffffffffu, l1, 1);
    l1 += __shfl_xor_sync(0xffffffffu, l1, 2);
    const float inv0 = 1.0f / l0, inv1 = 1.0f / l1;
    const size_t z0i = ((size_t)(b * 2048 + g0)) * 1024 + h * 64 + colq;
    const size_t z1i = z0i + (size_t)8 * 1024;
#pragma unroll
    for (int ni = 0; ni < 8; ni++) {
        split2_store(acc_o[ni][0] * inv0, acc_o[ni][1] * inv0,
                     &Zhi[z0i + ni * 8], &Zlo[z0i + ni * 8]);
        split2_store(acc_o[ni][2] * inv1, acc_o[ni][3] * inv1,
                     &Zhi[z1i + ni * 8], &Zlo[z1i + ni * 8]);
    }
}

// ---------------------------------------------------------------------------
// Launch
// ---------------------------------------------------------------------------
extern "C" void kernel_launch(void* const* d_in, const int* in_sizes, int n_in,
                              void* d_out, int out_size) {
    const float* x  = (const float*)d_in[0];  // (2,2048,1024)
    const float* Wq = (const float*)d_in[1];  // (1024,1024)
    const float* Wk = (const float*)d_in[2];  // (1024,64)
    const float* Wv = (const float*)d_in[3];  // (1024,64)
    const float* Wo = (const float*)d_in[4];  // (1024,1024)
    const float* bo = (const float*)d_in[5];  // (1024,)

    __nv_bfloat16 *QKVhi, *QKVlo, *Xhi, *Xlo, *Wthi, *Wtlo, *Wothi, *Wotlo, *Zhi, *Zlo;
    cudaGetSymbolAddress((void**)&QKVhi, g_QKVhi);
    cudaGetSymbolAddress((void**)&QKVlo, g_QKVlo);
    cudaGetSymbolAddress((void**)&Xhi,   g_Xhi);
    cudaGetSymbolAddress((void**)&Xlo,   g_Xlo);
    cudaGetSymbolAddress((void**)&Wthi,  g_Wthi);
    cudaGetSymbolAddress((void**)&Wtlo,  g_Wtlo);
    cudaGetSymbolAddress((void**)&Wothi, g_Wothi);
    cudaGetSymbolAddress((void**)&Wotlo, g_Wotlo);
    cudaGetSymbolAddress((void**)&Zhi,   g_Zhi);
    cudaGetSymbolAddress((void**)&Zlo,   g_Zlo);

    cudaFuncSetAttribute(hmma_gemm<true>,
                         cudaFuncAttributeMaxDynamicSharedMemorySize, GEMM_DSMEM);
    cudaFuncSetAttribute(hmma_gemm<false>,
                         cudaFuncAttributeMaxDynamicSharedMemorySize, GEMM_DSMEM);

    // 1) precision-split input / build weights (Wq pre-scaled by 1/8)
    split_f32_bf16<<<CDIV(4096 * 1024 / 4, 256), 256>>>(x, Xhi, Xlo, 4096 * 1024 / 4);
    build_wall_t<<<CDIV(1152 * 1024, 256), 256>>>(Wq, Wk, Wv, Wthi, Wtlo);
    build_wo_t<<<CDIV(1024 * 1024, 256), 256>>>(Wo, Wothi, Wotlo);

    // 2) QKV = X @ [Wq/8|Wk|Wv] -> split bf16 hi/lo directly
    hmma_gemm<true><<<dim3(1152 / 128, 4096 / 128), 256, GEMM_DSMEM>>>(
        Xhi, Xlo, Wthi, Wtlo, nullptr, nullptr, QKVhi, QKVlo, 1024, 1152);

    // 3) causal flash-attention MQA on HMMA (bf16 in, split bf16 out)
    attn_hmma<<<dim3(16, 16, 2), 256>>>(QKVhi, QKVlo, Zhi, Zlo);

    // 4) out = Z @ Wo + bo -> d_out (fp32)
    hmma_gemm<false><<<dim3(1024 / 128, 4096 / 128), 256, GEMM_DSMEM>>>(
        Zhi, Zlo, Wothi, Wotlo, (float*)d_out, bo, nullptr, nullptr, 1024, 1024);
}